// round 14
// baseline (speedup 1.0000x reference)
#include <cuda_runtime.h>
#include <cuda_bf16.h>
#include <cstdint>
#include <math.h>

#define Bn 2048
#define Hn 8

namespace {
// SMEM byte offsets (16B-aligned rows; padded strides, no swizzle)
constexpr int OFF_IDX = 0;                    // 128 int
constexpr int OFF_RED = 512;                  // 8 float
constexpr int OFF_XS  = 576;                  // fp32 [4][144] sum-exchange
constexpr int OFF_E   = 3072;                 // bf16 [128 f][128 k] stride 272B
constexpr int OFF_K   = OFF_E + 128 * 272;    // bf16 [128 f][64 p] stride 144B
constexpr int OFF_V   = OFF_K + 128 * 144;    // bf16 [128 f][64 p] stride 144B
constexpr int SMEM_BYTES = OFF_V + 128 * 144; // 74752 B -> 2 CTAs/SM, big L1D carveout
}

// W pre-packed as per-lane B-fragments (exactly what ldsm4 on the [n][k] tile
// would return): [m][h][kt][nt2][lane], m: 0=Wk 1=Wv 2=Wq 3=Wr.  512 KB.
__device__ uint4 gWfrag[4][Hn][8][4][32];
// Pre-packed out_w in per-thread fragment order: [h][w4][j][lane]
__device__ float4 gOwP[Hn][4][8][32];

__device__ __forceinline__ uint32_t pack_bf16x2(float lo, float hi) {
    uint32_t r;
    asm("cvt.rn.bf16x2.f32 %0, %1, %2;" : "=r"(r) : "f"(hi), "f"(lo));
    return r;
}

__global__ void prep_all(const float* __restrict__ Wk, const float* __restrict__ Wv,
                         const float* __restrict__ Wq, const float* __restrict__ Wr,
                         const float* __restrict__ ow)
{
    const int b = blockIdx.x;
    if (b < 128) {
        // B-fragment packing. ldmatrix m8n8.b16 distribution: lane holds row
        // (lane>>2), col-pair (lane&3); matrices 0..3 = {n+0..7,n+8..15} x {k,k+8}.
        int id = b * 256 + threadIdx.x;        // 32768 total
        int lane = id & 31, nt2 = (id >> 5) & 3, kt = (id >> 7) & 7;
        int h = (id >> 10) & 7, m = id >> 13;
        const float* Ws[4] = {Wk, Wv, Wq, Wr};
        const float* W = Ws[m];
        size_t ng = h * 64 + nt2 * 16 + (lane >> 2);   // global n column in W
        size_t ka = kt * 16 + 2 * (lane & 3);          // k row in W
        uint4 r;
        r.x = pack_bf16x2(W[ka * 512 + ng],           W[(ka + 1) * 512 + ng]);
        r.y = pack_bf16x2(W[(ka + 8) * 512 + ng],     W[(ka + 9) * 512 + ng]);
        r.z = pack_bf16x2(W[ka * 512 + ng + 8],       W[(ka + 1) * 512 + ng + 8]);
        r.w = pack_bf16x2(W[(ka + 8) * 512 + ng + 8], W[(ka + 9) * 512 + ng + 8]);
        gWfrag[m][h][kt][nt2][lane] = r;
    } else {
        // out_w packing into per-thread fragment order
        int id = (b - 128) * 256 + threadIdx.x;   // 8192 total
        int lane = id & 31, j = (id >> 5) & 7, w4 = (id >> 8) & 3, h = id >> 10;
        int frow = w4 * 16 + (lane >> 2), q = lane & 3;
        const float* p0 = ow + (size_t)frow * 512 + h * 64 + j * 8 + 2 * q;
        const float* p1 = ow + (size_t)(frow + 8) * 512 + h * 64 + j * 8 + 2 * q;
        gOwP[h][w4][j][lane] = make_float4(p0[0], p0[1], p1[0], p1[1]);
    }
}

__device__ __forceinline__ uint32_t smem_u32(const void* p) {
    uint32_t a;
    asm("{ .reg .u64 t; cvta.to.shared.u64 t, %1; cvt.u32.u64 %0, t; }" : "=r"(a) : "l"(p));
    return a;
}
__device__ __forceinline__ void ldsm4(uint32_t* r, uint32_t addr) {
    asm volatile("ldmatrix.sync.aligned.m8n8.x4.shared.b16 {%0,%1,%2,%3}, [%4];"
                 : "=r"(r[0]), "=r"(r[1]), "=r"(r[2]), "=r"(r[3]) : "r"(addr));
}
__device__ __forceinline__ void ldsm4t(uint32_t* r, uint32_t addr) {
    asm volatile("ldmatrix.sync.aligned.m8n8.x4.trans.shared.b16 {%0,%1,%2,%3}, [%4];"
                 : "=r"(r[0]), "=r"(r[1]), "=r"(r[2]), "=r"(r[3]) : "r"(addr));
}
__device__ __forceinline__ void mma16816(float* c, const uint32_t* a, uint32_t b0, uint32_t b1) {
    asm volatile(
        "mma.sync.aligned.m16n8k16.row.col.f32.bf16.bf16.f32 "
        "{%0,%1,%2,%3}, {%4,%5,%6,%7}, {%8,%9}, {%0,%1,%2,%3};"
        : "+f"(c[0]), "+f"(c[1]), "+f"(c[2]), "+f"(c[3])
        : "r"(a[0]), "r"(a[1]), "r"(a[2]), "r"(a[3]), "r"(b0), "r"(b1));
}
// per-group barrier: group = warps 0-3 (threads 0-127) or warps 4-7
__device__ __forceinline__ void bar_group(int gid) {
    asm volatile("bar.sync %0, 128;" :: "r"(gid + 1) : "memory");
}

// C[16x64] = E[16x128] @ W[128x64]; A from hoisted E frags, B = coalesced
// LDG.128 of pre-packed fragments (L1D/L2-resident).
__device__ __forceinline__ void run_proj(float acc[32], const uint32_t ea[8][4],
                                         const uint4* __restrict__ wf) {
#pragma unroll
    for (int i = 0; i < 32; i++) acc[i] = 0.f;
#pragma unroll
    for (int kt = 0; kt < 8; kt++) {
#pragma unroll
        for (int nt2 = 0; nt2 < 4; nt2++) {
            uint4 b = wf[(kt * 4 + nt2) * 32];
            mma16816(&acc[nt2 * 8],     ea[kt], b.x, b.y);
            mma16816(&acc[nt2 * 8 + 4], ea[kt], b.z, b.w);
        }
    }
}

__global__ __launch_bounds__(256, 2)
void autoint_mma(const int*   __restrict__ feat_index,
                 const float* __restrict__ emb,
                 const float* __restrict__ out_b,
                 float* __restrict__ out)
{
    extern __shared__ char sm[];
    const uint32_t smb = smem_u32(sm);
    const int tid  = threadIdx.x;
    const int wid  = tid >> 5;
    const int lane = tid & 31;
    const int m0   = wid * 16;        // warp's attention M-row base (0..112)
    const int bb   = wid >> 2;        // batch slot (0/1)
    const int w4   = wid & 3;         // warp index within batch

    int*   sIdx = (int*)(sm + OFF_IDX);
    float* sRed = (float*)(sm + OFF_RED);

    if (tid < 128) sIdx[tid] = feat_index[(size_t)blockIdx.x * 128 + tid];
    __syncthreads();

    // ---- gather E -> bf16 [128][136]
#pragma unroll
    for (int it = 0; it < 32; it++) {
        int i = tid + it * 256;
        int row = i >> 6, c2 = i & 63;
        float2 v = *(const float2*)(emb + (size_t)sIdx[row] * 128 + 2 * c2);
        *(uint32_t*)(sm + OFF_E + row * 272 + c2 * 4) = pack_bf16x2(v.x, v.y);
    }
    __syncthreads();

    // ---- hoist E A-fragments for this warp's 16 attention rows
    uint32_t ea[8][4];
#pragma unroll
    for (int kt = 0; kt < 8; kt++)
        ldsm4(ea[kt], smb + OFF_E + (m0 + (lane & 15)) * 272
                          + (kt * 16 + (lane >> 4) * 8) * 2);

    float oacc = 0.f;

    for (int h = 0; h < Hn; h++) {
        // ================= paired k|v projections, 32 rows/warp =================
        // warps 0-3: k (m=0) -> sK ; warps 4-7: v (m=1) -> sV. B direct from global.
        {
            const int mrow = w4 * 32;
            const uint4* __restrict__ wf = &gWfrag[(wid < 4) ? 0 : 1][h][0][0][lane];
            char* po = sm + ((wid < 4) ? OFF_K : OFF_V);
            float acc0[32], acc1[32];
#pragma unroll
            for (int i = 0; i < 32; i++) { acc0[i] = 0.f; acc1[i] = 0.f; }
#pragma unroll
            for (int kt = 0; kt < 8; kt++) {
                uint32_t a0[4], a1[4];
                uint32_t ab = smb + OFF_E + (mrow + (lane & 15)) * 272
                                  + (kt * 16 + (lane >> 4) * 8) * 2;
                ldsm4(a0, ab);
                ldsm4(a1, ab + 16 * 272);
#pragma unroll
                for (int nt2 = 0; nt2 < 4; nt2++) {
                    uint4 b = wf[(kt * 4 + nt2) * 32];
                    mma16816(&acc0[nt2 * 8],     a0, b.x, b.y);
                    mma16816(&acc0[nt2 * 8 + 4], a0, b.z, b.w);
                    mma16816(&acc1[nt2 * 8],     a1, b.x, b.y);
                    mma16816(&acc1[nt2 * 8 + 4], a1, b.z, b.w);
                }
            }
#pragma unroll
            for (int mt = 0; mt < 2; mt++) {
                const float* acc = mt ? acc1 : acc0;
                char* p0 = po + (mrow + mt * 16 + (lane >> 2)) * 144 + (lane & 3) * 4;
#pragma unroll
                for (int j = 0; j < 8; j++) {
                    *(uint32_t*)(p0 + j * 16)           = pack_bf16x2(acc[4*j],   acc[4*j+1]);
                    *(uint32_t*)(p0 + 8 * 144 + j * 16) = pack_bf16x2(acc[4*j+2], acc[4*j+3]);
                }
            }
        }
        __syncthreads();                           // sync 1: sK/sV visible

        // ================= q projection -> A-fragments =================
        uint32_t qf[4][4];
        {
            float acc[32];
            run_proj(acc, ea, &gWfrag[2][h][0][0][lane]);
#pragma unroll
            for (int kt = 0; kt < 4; kt++) {
                qf[kt][0] = pack_bf16x2(acc[8*kt],   acc[8*kt+1]);
                qf[kt][1] = pack_bf16x2(acc[8*kt+2], acc[8*kt+3]);
                qf[kt][2] = pack_bf16x2(acc[8*kt+4], acc[8*kt+5]);
                qf[kt][3] = pack_bf16x2(acc[8*kt+6], acc[8*kt+7]);
            }
        }

        // ================= scores: S[16x64] = q @ k^T (in registers) ==========
        float sacc[32];
#pragma unroll
        for (int i = 0; i < 32; i++) sacc[i] = 0.f;
#pragma unroll
        for (int kt = 0; kt < 4; kt++) {
#pragma unroll
            for (int nt2 = 0; nt2 < 4; nt2++) {
                uint32_t b[4];   // non-trans: B from sK[f_k][p] stride 144
                ldsm4(b, smb + OFF_K
                         + (bb * 64 + nt2 * 16 + (lane >> 4) * 8 + (lane & 7)) * 144
                         + (kt * 16 + ((lane >> 3) & 1) * 8) * 2);
                mma16816(&sacc[nt2 * 8],     qf[kt], b[0], b[1]);
                mma16816(&sacc[nt2 * 8 + 4], qf[kt], b[2], b[3]);
            }
        }

        // ================= softmax over QUERY axis (no max-shift: scores O(0.3))
#pragma unroll
        for (int i = 0; i < 32; i++) sacc[i] = __expf(sacc[i]);
        float M[16];
#pragma unroll
        for (int j = 0; j < 8; j++) {
            M[2*j]   = sacc[4*j]   + sacc[4*j+2];
            M[2*j+1] = sacc[4*j+1] + sacc[4*j+3];
        }
#pragma unroll
        for (int o = 4; o <= 16; o <<= 1)
#pragma unroll
            for (int i = 0; i < 16; i++)
                M[i] += __shfl_xor_sync(0xffffffffu, M[i], o);
        if (lane < 4) {
            char* px = sm + OFF_XS + w4 * 576 + (bb * 72 + lane * 2) * 4;
#pragma unroll
            for (int j = 0; j < 8; j++)
                *(float2*)(px + j * 32) = make_float2(M[2*j], M[2*j+1]);
        }
        bar_group(bb);      // sync D: XS exchange is strictly intra-batch-group
        uint32_t af[4][4];
        {
            const char* px = sm + OFF_XS + (bb * 72 + (lane & 3) * 2) * 4;
            float inv[16];
#pragma unroll
            for (int j = 0; j < 8; j++) {
                float2 t0 = *(const float2*)(px +         j * 32);
                float2 t1 = *(const float2*)(px +  576 +  j * 32);
                float2 t2 = *(const float2*)(px + 1152 +  j * 32);
                float2 t3 = *(const float2*)(px + 1728 +  j * 32);
                inv[2*j]   = 1.f / (t0.x + t1.x + t2.x + t3.x);
                inv[2*j+1] = 1.f / (t0.y + t1.y + t2.y + t3.y);
            }
            // att -> A-fragments directly (C layout == A layout)
#pragma unroll
            for (int kt = 0; kt < 4; kt++) {
                af[kt][0] = pack_bf16x2(sacc[8*kt]   * inv[4*kt],   sacc[8*kt+1] * inv[4*kt+1]);
                af[kt][1] = pack_bf16x2(sacc[8*kt+2] * inv[4*kt],   sacc[8*kt+3] * inv[4*kt+1]);
                af[kt][2] = pack_bf16x2(sacc[8*kt+4] * inv[4*kt+2], sacc[8*kt+5] * inv[4*kt+3]);
                af[kt][3] = pack_bf16x2(sacc[8*kt+6] * inv[4*kt+2], sacc[8*kt+7] * inv[4*kt+3]);
            }
        }

        // ================= AV[16x64] = att @ v =================
        float avacc[32];
#pragma unroll
        for (int i = 0; i < 32; i++) avacc[i] = 0.f;
#pragma unroll
        for (int kt = 0; kt < 4; kt++) {
#pragma unroll
            for (int nt2 = 0; nt2 < 4; nt2++) {
                uint32_t b[4];   // trans: B from sV[f_k][p] stride 144
                ldsm4t(b, smb + OFF_V
                          + (bb * 64 + kt * 16 + (lane & 15)) * 144
                          + (nt2 * 16 + (lane >> 4) * 8) * 2);
                mma16816(&avacc[nt2 * 8],     af[kt], b[0], b[1]);
                mma16816(&avacc[nt2 * 8 + 4], af[kt], b[2], b[3]);
            }
        }

        // ================= r projection (B direct from global) =================
        float racc[32];
        run_proj(racc, ea, &gWfrag[3][h][0][0][lane]);

        // ================= fused epilogue (pre-packed out_w, branchless) ======
        {
            const float4* owp = &gOwP[h][w4][0][lane];
#pragma unroll
            for (int j = 0; j < 8; j++) {
                float4 w = owp[j * 32];
                oacc += fmaxf(avacc[4*j]   + racc[4*j],   0.f) * w.x;
                oacc += fmaxf(avacc[4*j+1] + racc[4*j+1], 0.f) * w.y;
                oacc += fmaxf(avacc[4*j+2] + racc[4*j+2], 0.f) * w.z;
                oacc += fmaxf(avacc[4*j+3] + racc[4*j+3], 0.f) * w.w;
            }
        }
        __syncthreads();        // sync 2: all reads of sK/sV done before next head
    }

    // ---- reduce: warps 0-3 -> batch0, 4-7 -> batch1
#pragma unroll
    for (int o = 16; o; o >>= 1) oacc += __shfl_xor_sync(0xffffffffu, oacc, o);
    if (lane == 0) sRed[wid] = oacc;
    __syncthreads();
    if (tid == 0) {
        float s = sRed[0] + sRed[1] + sRed[2] + sRed[3] + out_b[0];
        out[blockIdx.x * 2] = 1.f / (1.f + expf(-s));
    }
    if (tid == 1) {
        float s = sRed[4] + sRed[5] + sRed[6] + sRed[7] + out_b[0];
        out[blockIdx.x * 2 + 1] = 1.f / (1.f + expf(-s));
    }
}

extern "C" void kernel_launch(void* const* d_in, const int* in_sizes, int n_in,
                              void* d_out, int out_size)
{
    const float* Wq = (const float*)d_in[2];
    const float* Wk = (const float*)d_in[3];
    const float* Wv = (const float*)d_in[4];
    const float* Wr = (const float*)d_in[5];

    cudaFuncSetAttribute(autoint_mma, cudaFuncAttributeMaxDynamicSharedMemorySize, SMEM_BYTES);

    prep_all<<<160, 256>>>(Wk, Wv, Wq, Wr, (const float*)d_in[6]);
    autoint_mma<<<Bn / 2, 256, SMEM_BYTES>>>(
        (const int*)d_in[0], (const float*)d_in[1],
        (const float*)d_in[7], (float*)d_out);
}

// round 15
// speedup vs baseline: 1.0693x; 1.0693x over previous
#include <cuda_runtime.h>
#include <cuda_bf16.h>
#include <cstdint>
#include <math.h>

#define Bn 2048
#define Hn 8

namespace {
// SMEM byte offsets (16B-aligned rows; padded strides, no swizzle)
constexpr int OFF_IDX = 0;                    // 128 int
constexpr int OFF_RED = 512;                  // 8 float
constexpr int OFF_XS  = 576;                  // fp32 [4][144] sum-exchange
constexpr int OFF_E   = 3072;                 // bf16 [128 f][128 k] stride 272B
constexpr int OFF_W0  = OFF_E  + 128 * 272;   // bf16 [64 n][128 k] stride 272B
constexpr int OFF_W1  = OFF_W0 + 64 * 272;    // bf16 [64 n][128 k]
constexpr int OFF_K   = OFF_W1 + 64 * 272;    // bf16 [128 f][64 p] stride 144B
constexpr int OFF_V   = OFF_K  + 128 * 144;   // bf16 [128 f][64 p] stride 144B
constexpr int SMEM_BYTES = OFF_V + 128 * 144; // 109568 B -> 2 CTAs/SM
}

// Pre-transposed bf16 weights: [m][h][n][k], m: 0=Wk 1=Wv 2=Wq 3=Wr
__device__ __nv_bfloat16 gWt[4][Hn][64][128];
// Pre-packed out_w in per-thread fragment order: [h][w4][j][lane]
__device__ float4 gOwP[Hn][4][8][32];

__global__ void prep_all(const float* __restrict__ Wk, const float* __restrict__ Wv,
                         const float* __restrict__ Wq, const float* __restrict__ Wr,
                         const float* __restrict__ ow)
{
    const int b = blockIdx.x;
    if (b < 256) {
        // W transpose+convert: e enumerates (m,h,k4,n), reads coalesced along n
        int e  = b * 256 + threadIdx.x;        // 65536 total
        int n  = e & 63, k4 = (e >> 6) & 31, h = (e >> 11) & 7, m = e >> 14;
        const float* Ws[4] = {Wk, Wv, Wq, Wr};
        const float* W = Ws[m];
        int k = k4 * 4;
        __nv_bfloat16 tmp[4];
#pragma unroll
        for (int j = 0; j < 4; j++)
            tmp[j] = __float2bfloat16(W[(size_t)(k + j) * 512 + h * 64 + n]);
        *(uint2*)&gWt[m][h][n][k] = *(const uint2*)tmp;
    } else {
        // out_w packing into per-thread fragment order
        int id = (b - 256) * 256 + threadIdx.x;   // 8192 total
        int lane = id & 31, j = (id >> 5) & 7, w4 = (id >> 8) & 3, h = id >> 10;
        int frow = w4 * 16 + (lane >> 2), q = lane & 3;
        const float* p0 = ow + (size_t)frow * 512 + h * 64 + j * 8 + 2 * q;
        const float* p1 = ow + (size_t)(frow + 8) * 512 + h * 64 + j * 8 + 2 * q;
        gOwP[h][w4][j][lane] = make_float4(p0[0], p0[1], p1[0], p1[1]);
    }
}

__device__ __forceinline__ uint32_t smem_u32(const void* p) {
    uint32_t a;
    asm("{ .reg .u64 t; cvta.to.shared.u64 t, %1; cvt.u32.u64 %0, t; }" : "=r"(a) : "l"(p));
    return a;
}
__device__ __forceinline__ uint32_t pack_bf16x2(float lo, float hi) {
    uint32_t r;
    asm("cvt.rn.bf16x2.f32 %0, %1, %2;" : "=r"(r) : "f"(hi), "f"(lo));
    return r;
}
__device__ __forceinline__ void ldsm4(uint32_t* r, uint32_t addr) {
    asm volatile("ldmatrix.sync.aligned.m8n8.x4.shared.b16 {%0,%1,%2,%3}, [%4];"
                 : "=r"(r[0]), "=r"(r[1]), "=r"(r[2]), "=r"(r[3]) : "r"(addr));
}
__device__ __forceinline__ void ldsm4t(uint32_t* r, uint32_t addr) {
    asm volatile("ldmatrix.sync.aligned.m8n8.x4.trans.shared.b16 {%0,%1,%2,%3}, [%4];"
                 : "=r"(r[0]), "=r"(r[1]), "=r"(r[2]), "=r"(r[3]) : "r"(addr));
}
__device__ __forceinline__ void mma16816(float* c, const uint32_t* a, uint32_t b0, uint32_t b1) {
    asm volatile(
        "mma.sync.aligned.m16n8k16.row.col.f32.bf16.bf16.f32 "
        "{%0,%1,%2,%3}, {%4,%5,%6,%7}, {%8,%9}, {%0,%1,%2,%3};"
        : "+f"(c[0]), "+f"(c[1]), "+f"(c[2]), "+f"(c[3])
        : "r"(a[0]), "r"(a[1]), "r"(a[2]), "r"(a[3]), "r"(b0), "r"(b1));
}

// B-fragment address for [n][k] bf16 tiles, stride 272B (non-trans ldsm4).
__device__ __forceinline__ uint32_t baddr(uint32_t base, int nt16, int kt16, int lane) {
    return base + (nt16 + (lane >> 4) * 8 + (lane & 7)) * 272
                + (kt16 + ((lane >> 3) & 1) * 8) * 2;
}

// C[16x64] = E[16x128] @ W[128x64]; A from hoisted E frags, B non-trans from [n][k]
__device__ __forceinline__ void run_proj(float acc[32], const uint32_t ea[8][4],
                                         uint32_t wbase, int lane) {
#pragma unroll
    for (int i = 0; i < 32; i++) acc[i] = 0.f;
#pragma unroll
    for (int kt = 0; kt < 8; kt++) {
#pragma unroll
        for (int nt2 = 0; nt2 < 4; nt2++) {
            uint32_t b[4];
            ldsm4(b, baddr(wbase, nt2 * 16, kt * 16, lane));
            mma16816(&acc[nt2 * 8],     ea[kt], b[0], b[1]);
            mma16816(&acc[nt2 * 8 + 4], ea[kt], b[2], b[3]);
        }
    }
}

// async-stage ONE pre-converted W tile into W0 or W1; one commit group
__device__ __forceinline__ void stage_tile_async(uint32_t smb, int buf, int m, int h, int tid) {
#pragma unroll
    for (int it = 0; it < 4; it++) {
        int j = tid + it * 256;                 // 1024 uint4 per tile
        int row = j >> 4, c = j & 15;
        uint32_t dst = smb + (buf ? OFF_W1 : OFF_W0) + row * 272 + c * 16;
        const void* src = &((const uint4*)&gWt[m][h][0][0])[j];
        asm volatile("cp.async.cg.shared.global [%0], [%1], 16;"
                     :: "r"(dst), "l"(src) : "memory");
    }
    asm volatile("cp.async.commit_group;" ::: "memory");
}
// stage the kv pair as one commit group
__device__ __forceinline__ void stage_kv_async(uint32_t smb, int h, int tid) {
#pragma unroll
    for (int it = 0; it < 8; it++) {
        int i = tid + it * 256;                 // 2048 uint4 total
        int m2 = i >> 10, j = i & 1023;
        int row = j >> 4, c = j & 15;
        uint32_t dst = smb + (m2 ? OFF_W1 : OFF_W0) + row * 272 + c * 16;
        const void* src = &((const uint4*)&gWt[m2][h][0][0])[j];
        asm volatile("cp.async.cg.shared.global [%0], [%1], 16;"
                     :: "r"(dst), "l"(src) : "memory");
    }
    asm volatile("cp.async.commit_group;" ::: "memory");
}
template <int N>
__device__ __forceinline__ void cp_wait() {
    asm volatile("cp.async.wait_group %0;" :: "n"(N) : "memory");
}

__global__ __launch_bounds__(256, 2)
void autoint_mma(const int*   __restrict__ feat_index,
                 const float* __restrict__ emb,
                 const float* __restrict__ out_b,
                 float* __restrict__ out)
{
    extern __shared__ char sm[];
    const uint32_t smb = smem_u32(sm);
    const int tid  = threadIdx.x;
    const int wid  = tid >> 5;
    const int lane = tid & 31;
    const int m0   = wid * 16;        // warp's attention M-row base (0..112)
    const int bb   = wid >> 2;        // batch slot (0/1)
    const int w4   = wid & 3;         // warp index within batch

    int*   sIdx = (int*)(sm + OFF_IDX);
    float* sRed = (float*)(sm + OFF_RED);

    // ---- prefetch kv(0) while we gather E
    stage_kv_async(smb, 0, tid);

    if (tid < 128) sIdx[tid] = feat_index[(size_t)blockIdx.x * 128 + tid];
    __syncthreads();

    // ---- gather E -> bf16 [128][136]
#pragma unroll
    for (int it = 0; it < 32; it++) {
        int i = tid + it * 256;
        int row = i >> 6, c2 = i & 63;
        float2 v = *(const float2*)(emb + (size_t)sIdx[row] * 128 + 2 * c2);
        *(uint32_t*)(sm + OFF_E + row * 272 + c2 * 4) = pack_bf16x2(v.x, v.y);
    }
    __syncthreads();

    // ---- hoist E A-fragments for this warp's 16 attention rows
    uint32_t ea[8][4];
#pragma unroll
    for (int kt = 0; kt < 8; kt++)
        ldsm4(ea[kt], smb + OFF_E + (m0 + (lane & 15)) * 272
                          + (kt * 16 + (lane >> 4) * 8) * 2);

    float oacc = 0.f;

    for (int h = 0; h < Hn; h++) {
        cp_wait<0>();
        __syncthreads();                                   // sync A: Wk/Wv ready

        // ================= paired k|v projections, 32 rows/warp =================
        // warps 0-3: k from W0 -> sK ; warps 4-7: v from W1 -> sV
        {
            const int mrow = w4 * 32;
            const uint32_t wb = smb + ((wid < 4) ? OFF_W0 : OFF_W1);
            char* po = sm + ((wid < 4) ? OFF_K : OFF_V);
            float acc0[32], acc1[32];
#pragma unroll
            for (int i = 0; i < 32; i++) { acc0[i] = 0.f; acc1[i] = 0.f; }
#pragma unroll
            for (int kt = 0; kt < 8; kt++) {
                uint32_t a0[4], a1[4];
                uint32_t ab = smb + OFF_E + (mrow + (lane & 15)) * 272
                                  + (kt * 16 + (lane >> 4) * 8) * 2;
                ldsm4(a0, ab);
                ldsm4(a1, ab + 16 * 272);
#pragma unroll
                for (int nt2 = 0; nt2 < 4; nt2++) {
                    uint32_t b[4];
                    ldsm4(b, baddr(wb, nt2 * 16, kt * 16, lane));
                    mma16816(&acc0[nt2 * 8],     a0, b[0], b[1]);
                    mma16816(&acc0[nt2 * 8 + 4], a0, b[2], b[3]);
                    mma16816(&acc1[nt2 * 8],     a1, b[0], b[1]);
                    mma16816(&acc1[nt2 * 8 + 4], a1, b[2], b[3]);
                }
            }
            __syncthreads();               // sync B: all warps done reading W0/W1

            // overlap: issue q then r copies (separate groups), then store kv frags
            stage_tile_async(smb, 0, 2, h, tid);   // q -> W0  (group q)
            stage_tile_async(smb, 1, 3, h, tid);   // r -> W1  (group r)
#pragma unroll
            for (int mt = 0; mt < 2; mt++) {
                const float* acc = mt ? acc1 : acc0;
                char* p0 = po + (mrow + mt * 16 + (lane >> 2)) * 144 + (lane & 3) * 4;
#pragma unroll
                for (int j = 0; j < 8; j++) {
                    *(uint32_t*)(p0 + j * 16)           = pack_bf16x2(acc[4*j],   acc[4*j+1]);
                    *(uint32_t*)(p0 + 8 * 144 + j * 16) = pack_bf16x2(acc[4*j+2], acc[4*j+3]);
                }
            }
        }
        cp_wait<1>();                      // q arrived (r may still fly)
        __syncthreads();                   // sync C: W0(q) + sK/sV visible

        // ================= q projection -> A-fragments =================
        uint32_t qf[4][4];
        {
            float acc[32];
            run_proj(acc, ea, smb + OFF_W0, lane);
#pragma unroll
            for (int kt = 0; kt < 4; kt++) {
                qf[kt][0] = pack_bf16x2(acc[8*kt],   acc[8*kt+1]);
                qf[kt][1] = pack_bf16x2(acc[8*kt+2], acc[8*kt+3]);
                qf[kt][2] = pack_bf16x2(acc[8*kt+4], acc[8*kt+5]);
                qf[kt][3] = pack_bf16x2(acc[8*kt+6], acc[8*kt+7]);
            }
        }

        // ================= scores: S[16x64] = q @ k^T (in registers) ==========
        float sacc[32];
#pragma unroll
        for (int i = 0; i < 32; i++) sacc[i] = 0.f;
#pragma unroll
        for (int kt = 0; kt < 4; kt++) {
#pragma unroll
            for (int nt2 = 0; nt2 < 4; nt2++) {
                uint32_t b[4];   // non-trans: B from sK[f_k][p] stride 144
                ldsm4(b, smb + OFF_K
                         + (bb * 64 + nt2 * 16 + (lane >> 4) * 8 + (lane & 7)) * 144
                         + (kt * 16 + ((lane >> 3) & 1) * 8) * 2);
                mma16816(&sacc[nt2 * 8],     qf[kt], b[0], b[1]);
                mma16816(&sacc[nt2 * 8 + 4], qf[kt], b[2], b[3]);
            }
        }

        // ================= softmax reduce (no max-shift: scores O(0.3)) =======
#pragma unroll
        for (int i = 0; i < 32; i++) sacc[i] = __expf(sacc[i]);
        {
            float M[16];
#pragma unroll
            for (int j = 0; j < 8; j++) {
                M[2*j]   = sacc[4*j]   + sacc[4*j+2];
                M[2*j+1] = sacc[4*j+1] + sacc[4*j+3];
            }
#pragma unroll
            for (int o = 4; o <= 16; o <<= 1)
#pragma unroll
                for (int i = 0; i < 16; i++)
                    M[i] += __shfl_xor_sync(0xffffffffu, M[i], o);
            if (lane < 4) {
                char* px = sm + OFF_XS + w4 * 576 + (bb * 72 + lane * 2) * 4;
#pragma unroll
                for (int j = 0; j < 8; j++)
                    *(float2*)(px + j * 32) = make_float2(M[2*j], M[2*j+1]);
            }
        }

        cp_wait<0>();                      // r arrived
        __syncthreads();                   // sync C2: W1(r) + XS visible

        // ================= r projection (W1) — hoisted before AV ==============
        float racc[32];
        run_proj(racc, ea, smb + OFF_W1, lane);
        __syncthreads();                   // sync E: W0/W1 free

        // overlap: prefetch next head's kv over af-pack + AV + epilogue
        if (h + 1 < Hn) stage_kv_async(smb, h + 1, tid);

        // ================= att -> A-fragments (inv fused per kt) ==============
        uint32_t af[4][4];
        {
            const char* px = sm + OFF_XS + (bb * 72 + (lane & 3) * 2) * 4;
#pragma unroll
            for (int kt = 0; kt < 4; kt++) {
                float inv[4];
#pragma unroll
                for (int jj = 0; jj < 2; jj++) {
                    int j = 2 * kt + jj;
                    float2 t0 = *(const float2*)(px +         j * 32);
                    float2 t1 = *(const float2*)(px +  576 +  j * 32);
                    float2 t2 = *(const float2*)(px + 1152 +  j * 32);
                    float2 t3 = *(const float2*)(px + 1728 +  j * 32);
                    inv[2*jj]   = 1.f / (t0.x + t1.x + t2.x + t3.x);
                    inv[2*jj+1] = 1.f / (t0.y + t1.y + t2.y + t3.y);
                }
                af[kt][0] = pack_bf16x2(sacc[8*kt]   * inv[0], sacc[8*kt+1] * inv[1]);
                af[kt][1] = pack_bf16x2(sacc[8*kt+2] * inv[0], sacc[8*kt+3] * inv[1]);
                af[kt][2] = pack_bf16x2(sacc[8*kt+4] * inv[2], sacc[8*kt+5] * inv[3]);
                af[kt][3] = pack_bf16x2(sacc[8*kt+6] * inv[2], sacc[8*kt+7] * inv[3]);
            }
        }

        // ================= AV[16x64] = att @ v =================
        float avacc[32];
#pragma unroll
        for (int i = 0; i < 32; i++) avacc[i] = 0.f;
#pragma unroll
        for (int kt = 0; kt < 4; kt++) {
#pragma unroll
            for (int nt2 = 0; nt2 < 4; nt2++) {
                uint32_t b[4];   // trans: B from sV[f_k][p] stride 144
                ldsm4t(b, smb + OFF_V
                          + (bb * 64 + kt * 16 + (lane & 15)) * 144
                          + (nt2 * 16 + (lane >> 4) * 8) * 2);
                mma16816(&avacc[nt2 * 8],     af[kt], b[0], b[1]);
                mma16816(&avacc[nt2 * 8 + 4], af[kt], b[2], b[3]);
            }
        }

        // ================= fused epilogue (pre-packed out_w, branchless) ======
        {
            const float4* owp = &gOwP[h][w4][0][lane];
#pragma unroll
            for (int j = 0; j < 8; j++) {
                float4 w = owp[j * 32];
                oacc += fmaxf(avacc[4*j]   + racc[4*j],   0.f) * w.x;
                oacc += fmaxf(avacc[4*j+1] + racc[4*j+1], 0.f) * w.y;
                oacc += fmaxf(avacc[4*j+2] + racc[4*j+2], 0.f) * w.z;
                oacc += fmaxf(avacc[4*j+3] + racc[4*j+3], 0.f) * w.w;
            }
        }
        // next head's sync A (full barrier) orders these sV reads vs new stores
    }

    // ---- reduce: warps 0-3 -> batch0, 4-7 -> batch1
#pragma unroll
    for (int o = 16; o; o >>= 1) oacc += __shfl_xor_sync(0xffffffffu, oacc, o);
    if (lane == 0) sRed[wid] = oacc;
    __syncthreads();
    if (tid == 0) {
        float s = sRed[0] + sRed[1] + sRed[2] + sRed[3] + out_b[0];
        out[blockIdx.x * 2] = 1.f / (1.f + expf(-s));
    }
    if (tid == 1) {
        float s = sRed[4] + sRed[5] + sRed[6] + sRed[7] + out_b[0];
        out[blockIdx.x * 2 + 1] = 1.f / (1.f + expf(-s));
    }
}

extern "C" void kernel_launch(void* const* d_in, const int* in_sizes, int n_in,
                              void* d_out, int out_size)
{
    const float* Wq = (const float*)d_in[2];
    const float* Wk = (const float*)d_in[3];
    const float* Wv = (const float*)d_in[4];
    const float* Wr = (const float*)d_in[5];

    cudaFuncSetAttribute(autoint_mma, cudaFuncAttributeMaxDynamicSharedMemorySize, SMEM_BYTES);

    prep_all<<<288, 256>>>(Wk, Wv, Wq, Wr, (const float*)d_in[6]);
    autoint_mma<<<Bn / 2, 256, SMEM_BYTES>>>(
        (const int*)d_in[0], (const float*)d_in[1],
        (const float*)d_in[7], (float*)d_out);
}

// round 16
// speedup vs baseline: 1.1014x; 1.0301x over previous
#include <cuda_runtime.h>
#include <cuda_bf16.h>
#include <cstdint>
#include <math.h>

#define Bn 2048
#define Hn 8

namespace {
// SMEM byte offsets (16B-aligned rows; padded strides, no swizzle)
constexpr int OFF_IDX = 0;                    // 128 int
constexpr int OFF_RED = 512;                  // 8 float
constexpr int OFF_XS  = 576;                  // fp32 [4][144] sum-exchange
constexpr int OFF_E   = 3072;                 // bf16 [128 f][128 k] stride 272B
constexpr int OFF_W0  = OFF_E  + 128 * 272;   // bf16 [64 n][128 k] stride 272B
constexpr int OFF_W1  = OFF_W0 + 64 * 272;    // bf16 [64 n][128 k]
constexpr int OFF_K   = OFF_W1 + 64 * 272;    // bf16 [128 f][64 p] stride 144B
constexpr int OFF_V   = OFF_K  + 128 * 144;   // bf16 [128 f][64 p] stride 144B
constexpr int SMEM_BYTES = OFF_V + 128 * 144; // 109568 B -> 2 CTAs/SM
}

// Pre-transposed bf16 weights: [m][h][n][k], m: 0=Wk 1=Wv 2=Wq 3=Wr
__device__ __nv_bfloat16 gWt[4][Hn][64][128];
// Pre-packed out_w in per-thread fragment order: [h][w4][j][lane]
__device__ float4 gOwP[Hn][4][8][32];

__global__ void prep_all(const float* __restrict__ Wk, const float* __restrict__ Wv,
                         const float* __restrict__ Wq, const float* __restrict__ Wr,
                         const float* __restrict__ ow)
{
    const int b = blockIdx.x;
    if (b < 256) {
        // W transpose+convert: e enumerates (m,h,k4,n), reads coalesced along n
        int e  = b * 256 + threadIdx.x;        // 65536 total
        int n  = e & 63, k4 = (e >> 6) & 31, h = (e >> 11) & 7, m = e >> 14;
        const float* Ws[4] = {Wk, Wv, Wq, Wr};
        const float* W = Ws[m];
        int k = k4 * 4;
        __nv_bfloat16 tmp[4];
#pragma unroll
        for (int j = 0; j < 4; j++)
            tmp[j] = __float2bfloat16(W[(size_t)(k + j) * 512 + h * 64 + n]);
        *(uint2*)&gWt[m][h][n][k] = *(const uint2*)tmp;
    } else {
        // out_w packing into per-thread fragment order
        int id = (b - 256) * 256 + threadIdx.x;   // 8192 total
        int lane = id & 31, j = (id >> 5) & 7, w4 = (id >> 8) & 3, h = id >> 10;
        int frow = w4 * 16 + (lane >> 2), q = lane & 3;
        const float* p0 = ow + (size_t)frow * 512 + h * 64 + j * 8 + 2 * q;
        const float* p1 = ow + (size_t)(frow + 8) * 512 + h * 64 + j * 8 + 2 * q;
        gOwP[h][w4][j][lane] = make_float4(p0[0], p0[1], p1[0], p1[1]);
    }
}

__device__ __forceinline__ uint32_t smem_u32(const void* p) {
    uint32_t a;
    asm("{ .reg .u64 t; cvta.to.shared.u64 t, %1; cvt.u32.u64 %0, t; }" : "=r"(a) : "l"(p));
    return a;
}
__device__ __forceinline__ uint32_t pack_bf16x2(float lo, float hi) {
    uint32_t r;
    asm("cvt.rn.bf16x2.f32 %0, %1, %2;" : "=r"(r) : "f"(hi), "f"(lo));
    return r;
}
__device__ __forceinline__ void ldsm4(uint32_t* r, uint32_t addr) {
    asm volatile("ldmatrix.sync.aligned.m8n8.x4.shared.b16 {%0,%1,%2,%3}, [%4];"
                 : "=r"(r[0]), "=r"(r[1]), "=r"(r[2]), "=r"(r[3]) : "r"(addr));
}
__device__ __forceinline__ void ldsm4t(uint32_t* r, uint32_t addr) {
    asm volatile("ldmatrix.sync.aligned.m8n8.x4.trans.shared.b16 {%0,%1,%2,%3}, [%4];"
                 : "=r"(r[0]), "=r"(r[1]), "=r"(r[2]), "=r"(r[3]) : "r"(addr));
}
__device__ __forceinline__ void mma16816(float* c, const uint32_t* a, uint32_t b0, uint32_t b1) {
    asm volatile(
        "mma.sync.aligned.m16n8k16.row.col.f32.bf16.bf16.f32 "
        "{%0,%1,%2,%3}, {%4,%5,%6,%7}, {%8,%9}, {%0,%1,%2,%3};"
        : "+f"(c[0]), "+f"(c[1]), "+f"(c[2]), "+f"(c[3])
        : "r"(a[0]), "r"(a[1]), "r"(a[2]), "r"(a[3]), "r"(b0), "r"(b1));
}
// per-group barrier: group = warps 0-3 (threads 0-127) or warps 4-7
__device__ __forceinline__ void bar_group(int gid) {
    asm volatile("bar.sync %0, 128;" :: "r"(gid + 1) : "memory");
}

// B-fragment address for [n][k] bf16 tiles, stride 272B (non-trans ldsm4).
__device__ __forceinline__ uint32_t baddr(uint32_t base, int nt16, int kt16, int lane) {
    return base + (nt16 + (lane >> 4) * 8 + (lane & 7)) * 272
                + (kt16 + ((lane >> 3) & 1) * 8) * 2;
}

// C[16x64] = E[16x128] @ W[128x64]; A from hoisted E frags, B non-trans from [n][k]
__device__ __forceinline__ void run_proj(float acc[32], const uint32_t ea[8][4],
                                         uint32_t wbase, int lane) {
#pragma unroll
    for (int i = 0; i < 32; i++) acc[i] = 0.f;
#pragma unroll
    for (int kt = 0; kt < 8; kt++) {
#pragma unroll
        for (int nt2 = 0; nt2 < 4; nt2++) {
            uint32_t b[4];
            ldsm4(b, baddr(wbase, nt2 * 16, kt * 16, lane));
            mma16816(&acc[nt2 * 8],     ea[kt], b[0], b[1]);
            mma16816(&acc[nt2 * 8 + 4], ea[kt], b[2], b[3]);
        }
    }
}

// stage q/r split by thread group: threads 0-127 copy q->W0, 128-255 copy r->W1.
// Writers stay in the same 128-thread group as the buffer's readers.
__device__ __forceinline__ void stage_half_async(uint32_t smb, int h, int tid) {
    const int half = tid >> 7;                 // 0: q, 1: r
    const int t    = tid & 127;
    const uint32_t base = smb + (half ? OFF_W1 : OFF_W0);
    const uint4* __restrict__ src = (const uint4*)&gWt[2 + half][h][0][0];
#pragma unroll
    for (int it = 0; it < 8; it++) {
        int j = t + it * 128;                  // 1024 uint4 per tile
        int row = j >> 4, c = j & 15;
        asm volatile("cp.async.cg.shared.global [%0], [%1], 16;"
                     :: "r"(base + row * 272 + c * 16), "l"(src + j) : "memory");
    }
    asm volatile("cp.async.commit_group;" ::: "memory");
}
// stage the kv pair as one commit group (all threads, both buffers)
__device__ __forceinline__ void stage_kv_async(uint32_t smb, int h, int tid) {
#pragma unroll
    for (int it = 0; it < 8; it++) {
        int i = tid + it * 256;                 // 2048 uint4 total
        int m2 = i >> 10, j = i & 1023;
        int row = j >> 4, c = j & 15;
        uint32_t dst = smb + (m2 ? OFF_W1 : OFF_W0) + row * 272 + c * 16;
        const void* src = &((const uint4*)&gWt[m2][h][0][0])[j];
        asm volatile("cp.async.cg.shared.global [%0], [%1], 16;"
                     :: "r"(dst), "l"(src) : "memory");
    }
    asm volatile("cp.async.commit_group;" ::: "memory");
}
__device__ __forceinline__ void cp_wait_all() {
    asm volatile("cp.async.wait_group 0;" ::: "memory");
}

__global__ __launch_bounds__(256, 2)
void autoint_mma(const int*   __restrict__ feat_index,
                 const float* __restrict__ emb,
                 const float* __restrict__ out_b,
                 float* __restrict__ out)
{
    extern __shared__ char sm[];
    const uint32_t smb = smem_u32(sm);
    const int tid  = threadIdx.x;
    const int wid  = tid >> 5;
    const int lane = tid & 31;
    const int m0   = wid * 16;        // warp's attention M-row base (0..112)
    const int bb   = wid >> 2;        // batch slot (0/1) == thread group
    const int w4   = wid & 3;         // warp index within batch

    int*   sIdx = (int*)(sm + OFF_IDX);
    float* sRed = (float*)(sm + OFF_RED);

    // ---- prefetch kv(0) while we gather E
    stage_kv_async(smb, 0, tid);

    if (tid < 128) sIdx[tid] = feat_index[(size_t)blockIdx.x * 128 + tid];
    __syncthreads();

    // ---- gather E -> bf16 [128][136]
#pragma unroll
    for (int it = 0; it < 32; it++) {
        int i = tid + it * 256;
        int row = i >> 6, c2 = i & 63;
        float2 v = *(const float2*)(emb + (size_t)sIdx[row] * 128 + 2 * c2);
        *(uint32_t*)(sm + OFF_E + row * 272 + c2 * 4) = pack_bf16x2(v.x, v.y);
    }
    __syncthreads();

    // ---- hoist E A-fragments for this warp's 16 attention rows
    uint32_t ea[8][4];
#pragma unroll
    for (int kt = 0; kt < 8; kt++)
        ldsm4(ea[kt], smb + OFF_E + (m0 + (lane & 15)) * 272
                          + (kt * 16 + (lane >> 4) * 8) * 2);

    float oacc = 0.f;

    for (int h = 0; h < Hn; h++) {
        cp_wait_all();
        __syncthreads();                                   // sync A: Wk/Wv ready

        // ================= paired k|v projections, 32 rows/warp =================
        // warps 0-3: k from W0 -> sK ; warps 4-7: v from W1 -> sV
        {
            const int mrow = w4 * 32;
            const uint32_t wb = smb + ((wid < 4) ? OFF_W0 : OFF_W1);
            char* po = sm + ((wid < 4) ? OFF_K : OFF_V);
            float acc0[32], acc1[32];
#pragma unroll
            for (int i = 0; i < 32; i++) { acc0[i] = 0.f; acc1[i] = 0.f; }
#pragma unroll
            for (int kt = 0; kt < 8; kt++) {
                uint32_t a0[4], a1[4];
                uint32_t ab = smb + OFF_E + (mrow + (lane & 15)) * 272
                                  + (kt * 16 + (lane >> 4) * 8) * 2;
                ldsm4(a0, ab);
                ldsm4(a1, ab + 16 * 272);
#pragma unroll
                for (int nt2 = 0; nt2 < 4; nt2++) {
                    uint32_t b[4];
                    ldsm4(b, baddr(wb, nt2 * 16, kt * 16, lane));
                    mma16816(&acc0[nt2 * 8],     a0, b[0], b[1]);
                    mma16816(&acc0[nt2 * 8 + 4], a0, b[2], b[3]);
                    mma16816(&acc1[nt2 * 8],     a1, b[0], b[1]);
                    mma16816(&acc1[nt2 * 8 + 4], a1, b[2], b[3]);
                }
            }
            // sync B (relaxed): W0 readers/writers are group 0; W1's are group 1.
            bar_group(bb);

            // overlap: issue own half's q/r copy, then store kv fragments
            stage_half_async(smb, h, tid);
#pragma unroll
            for (int mt = 0; mt < 2; mt++) {
                const float* acc = mt ? acc1 : acc0;
                char* p0 = po + (mrow + mt * 16 + (lane >> 2)) * 144 + (lane & 3) * 4;
#pragma unroll
                for (int j = 0; j < 8; j++) {
                    *(uint32_t*)(p0 + j * 16)           = pack_bf16x2(acc[4*j],   acc[4*j+1]);
                    *(uint32_t*)(p0 + 8 * 144 + j * 16) = pack_bf16x2(acc[4*j+2], acc[4*j+3]);
                }
            }
        }
        cp_wait_all();                     // own half's copy done
        __syncthreads();                   // sync C: q+r (both halves) + sK/sV visible

        // ================= q projection -> A-fragments =================
        uint32_t qf[4][4];
        {
            float acc[32];
            run_proj(acc, ea, smb + OFF_W0, lane);
#pragma unroll
            for (int kt = 0; kt < 4; kt++) {
                qf[kt][0] = pack_bf16x2(acc[8*kt],   acc[8*kt+1]);
                qf[kt][1] = pack_bf16x2(acc[8*kt+2], acc[8*kt+3]);
                qf[kt][2] = pack_bf16x2(acc[8*kt+4], acc[8*kt+5]);
                qf[kt][3] = pack_bf16x2(acc[8*kt+6], acc[8*kt+7]);
            }
        }

        // ================= scores: S[16x64] = q @ k^T (in registers) ==========
        float sacc[32];
#pragma unroll
        for (int i = 0; i < 32; i++) sacc[i] = 0.f;
#pragma unroll
        for (int kt = 0; kt < 4; kt++) {
#pragma unroll
            for (int nt2 = 0; nt2 < 4; nt2++) {
                uint32_t b[4];   // non-trans: B from sK[f_k][p] stride 144
                ldsm4(b, smb + OFF_K
                         + (bb * 64 + nt2 * 16 + (lane >> 4) * 8 + (lane & 7)) * 144
                         + (kt * 16 + ((lane >> 3) & 1) * 8) * 2);
                mma16816(&sacc[nt2 * 8],     qf[kt], b[0], b[1]);
                mma16816(&sacc[nt2 * 8 + 4], qf[kt], b[2], b[3]);
            }
        }

        // ================= softmax over QUERY axis (no max-shift: scores O(0.3))
#pragma unroll
        for (int i = 0; i < 32; i++) sacc[i] = __expf(sacc[i]);
        float M[16];
#pragma unroll
        for (int j = 0; j < 8; j++) {
            M[2*j]   = sacc[4*j]   + sacc[4*j+2];
            M[2*j+1] = sacc[4*j+1] + sacc[4*j+3];
        }
#pragma unroll
        for (int o = 4; o <= 16; o <<= 1)
#pragma unroll
            for (int i = 0; i < 16; i++)
                M[i] += __shfl_xor_sync(0xffffffffu, M[i], o);
        if (lane < 4) {
            char* px = sm + OFF_XS + w4 * 576 + (bb * 72 + lane * 2) * 4;
#pragma unroll
            for (int j = 0; j < 8; j++)
                *(float2*)(px + j * 32) = make_float2(M[2*j], M[2*j+1]);
        }
        bar_group(bb);      // sync D: XS exchange is strictly intra-batch-group
        uint32_t af[4][4];
        {
            const char* px = sm + OFF_XS + (bb * 72 + (lane & 3) * 2) * 4;
            float inv[16];
#pragma unroll
            for (int j = 0; j < 8; j++) {
                float2 t0 = *(const float2*)(px +         j * 32);
                float2 t1 = *(const float2*)(px +  576 +  j * 32);
                float2 t2 = *(const float2*)(px + 1152 +  j * 32);
                float2 t3 = *(const float2*)(px + 1728 +  j * 32);
                inv[2*j]   = 1.f / (t0.x + t1.x + t2.x + t3.x);
                inv[2*j+1] = 1.f / (t0.y + t1.y + t2.y + t3.y);
            }
            // att -> A-fragments directly (C layout == A layout)
#pragma unroll
            for (int kt = 0; kt < 4; kt++) {
                af[kt][0] = pack_bf16x2(sacc[8*kt]   * inv[4*kt],   sacc[8*kt+1] * inv[4*kt+1]);
                af[kt][1] = pack_bf16x2(sacc[8*kt+2] * inv[4*kt],   sacc[8*kt+3] * inv[4*kt+1]);
                af[kt][2] = pack_bf16x2(sacc[8*kt+4] * inv[4*kt+2], sacc[8*kt+5] * inv[4*kt+3]);
                af[kt][3] = pack_bf16x2(sacc[8*kt+6] * inv[4*kt+2], sacc[8*kt+7] * inv[4*kt+3]);
            }
        }

        // ================= AV[16x64] = att @ v =================
        float avacc[32];
#pragma unroll
        for (int i = 0; i < 32; i++) avacc[i] = 0.f;
#pragma unroll
        for (int kt = 0; kt < 4; kt++) {
#pragma unroll
            for (int nt2 = 0; nt2 < 4; nt2++) {
                uint32_t b[4];   // trans: B from sV[f_k][p] stride 144
                ldsm4t(b, smb + OFF_V
                          + (bb * 64 + kt * 16 + (lane & 15)) * 144
                          + (nt2 * 16 + (lane >> 4) * 8) * 2);
                mma16816(&avacc[nt2 * 8],     af[kt], b[0], b[1]);
                mma16816(&avacc[nt2 * 8 + 4], af[kt], b[2], b[3]);
            }
        }

        // ================= r projection (W1) =================
        float racc[32];
        run_proj(racc, ea, smb + OFF_W1, lane);
        __syncthreads();                   // sync E: all done reading W0/W1/tiles

        // overlap: prefetch next head's kv while we run the epilogue
        if (h + 1 < Hn) stage_kv_async(smb, h + 1, tid);

        // ================= fused epilogue (pre-packed out_w, branchless) ======
        {
            const float4* owp = &gOwP[h][w4][0][lane];
#pragma unroll
            for (int j = 0; j < 8; j++) {
                float4 w = owp[j * 32];
                oacc += fmaxf(avacc[4*j]   + racc[4*j],   0.f) * w.x;
                oacc += fmaxf(avacc[4*j+1] + racc[4*j+1], 0.f) * w.y;
                oacc += fmaxf(avacc[4*j+2] + racc[4*j+2], 0.f) * w.z;
                oacc += fmaxf(avacc[4*j+3] + racc[4*j+3], 0.f) * w.w;
            }
        }
        // next head's sync A (full barrier) orders these sV reads vs new stores
    }

    // ---- reduce: warps 0-3 -> batch0, 4-7 -> batch1
#pragma unroll
    for (int o = 16; o; o >>= 1) oacc += __shfl_xor_sync(0xffffffffu, oacc, o);
    if (lane == 0) sRed[wid] = oacc;
    __syncthreads();
    if (tid == 0) {
        float s = sRed[0] + sRed[1] + sRed[2] + sRed[3] + out_b[0];
        out[blockIdx.x * 2] = 1.f / (1.f + expf(-s));
    }
    if (tid == 1) {
        float s = sRed[4] + sRed[5] + sRed[6] + sRed[7] + out_b[0];
        out[blockIdx.x * 2 + 1] = 1.f / (1.f + expf(-s));
    }
}

extern "C" void kernel_launch(void* const* d_in, const int* in_sizes, int n_in,
                              void* d_out, int out_size)
{
    const float* Wq = (const float*)d_in[2];
    const float* Wk = (const float*)d_in[3];
    const float* Wv = (const float*)d_in[4];
    const float* Wr = (const float*)d_in[5];

    cudaFuncSetAttribute(autoint_mma, cudaFuncAttributeMaxDynamicSharedMemorySize, SMEM_BYTES);

    prep_all<<<288, 256>>>(Wk, Wv, Wq, Wr, (const float*)d_in[6]);
    autoint_mma<<<Bn / 2, 256, SMEM_BYTES>>>(
        (const int*)d_in[0], (const float*)d_in[1],
        (const float*)d_in[7], (float*)d_out);
}